// round 8
// baseline (speedup 1.0000x reference)
#include <cuda_runtime.h>
#include <cuda_bf16.h>
#include <cstdint>

#define FEAT_D 128
#define MAX_NODES 50176
#define MAX_EDGES 650240

// ---- scratch (__device__ globals; no allocation allowed) ----
__device__ float g_h[MAX_NODES * FEAT_D];       // pooled features after GEMM1
__device__ float g_neigh[MAX_NODES * FEAT_D];   // per-node max-pooled neighborhood
__device__ int   g_deg[MAX_NODES];
__device__ int   g_incl[MAX_NODES];
__device__ int   g_bsum[256];
__device__ int   g_bbase[256];
__device__ int   g_offs[MAX_NODES + 1];
__device__ int   g_cursor[MAX_NODES];
__device__ int2  g_rec[MAX_EDGES];
__device__ int   g_idx64;
// bf16 hi/lo weight images, row-major [128][K]: W_pool at 0 (K=128), W_neigh at 128*128 (K=256)
__device__ __nv_bfloat16 g_whi[128 * 384];
__device__ __nv_bfloat16 g_wlo[128 * 384];

// ============================ helpers ======================================
__device__ __forceinline__ uint32_t smem_to_u32(const void* p) {
    uint32_t a;
    asm("{ .reg .u64 t; cvta.to.shared.u64 t, %1; cvt.u32.u64 %0, t; }" : "=r"(a) : "l"(p));
    return a;
}
__device__ __forceinline__ uint32_t pack_bf2(__nv_bfloat162 v) {
    return ((uint32_t)__bfloat16_as_ushort(v.y) << 16) |
            (uint32_t)__bfloat16_as_ushort(v.x);
}
__device__ __forceinline__ void ldsm_x4(uint32_t* r, uint32_t addr) {
    asm volatile("ldmatrix.sync.aligned.m8n8.x4.shared.b16 {%0,%1,%2,%3}, [%4];"
        : "=r"(r[0]), "=r"(r[1]), "=r"(r[2]), "=r"(r[3]) : "r"(addr));
}
__device__ __forceinline__ void mma16816(float* c, const uint32_t* a, const uint32_t* b) {
    asm volatile("mma.sync.aligned.m16n8k16.row.col.f32.bf16.bf16.f32 "
        "{%0,%1,%2,%3}, {%4,%5,%6,%7}, {%8,%9}, {%0,%1,%2,%3};"
        : "+f"(c[0]), "+f"(c[1]), "+f"(c[2]), "+f"(c[3])
        : "r"(a[0]), "r"(a[1]), "r"(a[2]), "r"(a[3]), "r"(b[0]), "r"(b[1]));
}

// ============================ misc kernels =================================
__global__ void detect_kernel(const void* src, int E, int N) {
    if (threadIdx.x == 0 && blockIdx.x == 0) {
        const long long* p = (const long long*)src;
        int n = E < 256 ? E : 256;
        int ok = 1;
        for (int i = 0; i < n; i++) {
            long long v = p[i];
            if (v < 0 || v >= (long long)N) { ok = 0; break; }
        }
        g_idx64 = ok;
    }
}
__device__ __forceinline__ int load_idx(const void* p, int i) {
    return g_idx64 ? (int)((const long long*)p)[i] : ((const int*)p)[i];
}

// Split W (row-major [128][K] fp32) into bf16 hi/lo row-major images.
__global__ void prep_w_kernel(const float* __restrict__ W, int K, int wofs) {
    int e = blockIdx.x * blockDim.x + threadIdx.x;
    if (e >= 128 * K) return;
    float v = W[e];
    __nv_bfloat16 h = __float2bfloat16(v);
    __nv_bfloat16 l = __float2bfloat16(v - __bfloat162float(h));
    g_whi[wofs + e] = h;
    g_wlo[wofs + e] = l;
}

// ============================ CSR build ====================================
__global__ void zero_deg_kernel(int n) {
    int i = blockIdx.x * blockDim.x + threadIdx.x;
    if (i < n) g_deg[i] = 0;
}
__global__ void count_kernel(const void* __restrict__ dst, int E, int N) {
    int e = blockIdx.x * blockDim.x + threadIdx.x;
    if (e >= E) return;
    int d = load_idx(dst, e);
    if ((unsigned)d < (unsigned)N) atomicAdd(&g_deg[d], 1);
}
__global__ void scan1_kernel(int n) {
    __shared__ int s[512];
    int tid = threadIdx.x;
    int i = blockIdx.x * 512 + tid;
    int v = (i < n) ? g_deg[i] : 0;
    s[tid] = v;
    __syncthreads();
    #pragma unroll
    for (int off = 1; off < 512; off <<= 1) {
        int t = (tid >= off) ? s[tid - off] : 0;
        __syncthreads();
        s[tid] += t;
        __syncthreads();
    }
    if (i < n) g_incl[i] = s[tid];
    if (tid == 511) g_bsum[blockIdx.x] = s[511];
}
__global__ void scan2_kernel(int nblocks) {
    __shared__ int s[256];
    int tid = threadIdx.x;
    int v = (tid < nblocks) ? g_bsum[tid] : 0;
    s[tid] = v;
    __syncthreads();
    #pragma unroll
    for (int off = 1; off < 256; off <<= 1) {
        int t = (tid >= off) ? s[tid - off] : 0;
        __syncthreads();
        s[tid] += t;
        __syncthreads();
    }
    if (tid < nblocks) g_bbase[tid] = s[tid] - v;
}
__global__ void scan3_kernel(int n, int E) {
    int i = blockIdx.x * 512 + threadIdx.x;
    if (i >= n) return;
    int ex = g_incl[i] - g_deg[i] + g_bbase[blockIdx.x];
    g_offs[i]   = ex;
    g_cursor[i] = ex;
    if (i == n - 1) g_offs[n] = E;
}
__global__ void scatter_kernel(const float* __restrict__ weight,
                               const void* __restrict__ src,
                               const void* __restrict__ dst,
                               int E, int N) {
    int e = blockIdx.x * blockDim.x + threadIdx.x;
    if (e >= E) return;
    int d = load_idx(dst, e);
    int s = load_idx(src, e);
    if ((unsigned)d >= (unsigned)N || (unsigned)s >= (unsigned)N) return;
    int pos = atomicAdd(&g_cursor[d], 1);
    g_rec[pos] = make_int2(s, __float_as_int(weight[e]));
}

// ============================ node max =====================================
__global__ void __launch_bounds__(256)
nodemax_kernel(int N) {
    int warp = (blockIdx.x * blockDim.x + threadIdx.x) >> 5;
    int lane = threadIdx.x & 31;
    if (warp >= N) return;

    int beg = g_offs[warp];
    int end = g_offs[warp + 1];

    float* outp = g_neigh + (size_t)warp * FEAT_D + lane * 4;
    if (beg == end) {
        *(float4*)outp = make_float4(0.f, 0.f, 0.f, 0.f);
        return;
    }
    const float NEG = -3.402823466e+38f;
    float4 m = make_float4(NEG, NEG, NEG, NEG);
    int e = beg;
    for (; e + 4 <= end; e += 4) {
        int2 r0 = g_rec[e + 0];
        int2 r1 = g_rec[e + 1];
        int2 r2 = g_rec[e + 2];
        int2 r3 = g_rec[e + 3];
        float4 v0 = *(const float4*)(g_h + (size_t)r0.x * FEAT_D + lane * 4);
        float4 v1 = *(const float4*)(g_h + (size_t)r1.x * FEAT_D + lane * 4);
        float4 v2 = *(const float4*)(g_h + (size_t)r2.x * FEAT_D + lane * 4);
        float4 v3 = *(const float4*)(g_h + (size_t)r3.x * FEAT_D + lane * 4);
        float w0 = __int_as_float(r0.y), w1 = __int_as_float(r1.y);
        float w2 = __int_as_float(r2.y), w3 = __int_as_float(r3.y);
        m.x = fmaxf(m.x, v0.x * w0); m.y = fmaxf(m.y, v0.y * w0);
        m.z = fmaxf(m.z, v0.z * w0); m.w = fmaxf(m.w, v0.w * w0);
        m.x = fmaxf(m.x, v1.x * w1); m.y = fmaxf(m.y, v1.y * w1);
        m.z = fmaxf(m.z, v1.z * w1); m.w = fmaxf(m.w, v1.w * w1);
        m.x = fmaxf(m.x, v2.x * w2); m.y = fmaxf(m.y, v2.y * w2);
        m.z = fmaxf(m.z, v2.z * w2); m.w = fmaxf(m.w, v2.w * w2);
        m.x = fmaxf(m.x, v3.x * w3); m.y = fmaxf(m.y, v3.y * w3);
        m.z = fmaxf(m.z, v3.z * w3); m.w = fmaxf(m.w, v3.w * w3);
    }
    for (; e < end; e++) {
        int2 r = g_rec[e];
        float w = __int_as_float(r.y);
        float4 v = *(const float4*)(g_h + (size_t)r.x * FEAT_D + lane * 4);
        m.x = fmaxf(m.x, v.x * w); m.y = fmaxf(m.y, v.y * w);
        m.z = fmaxf(m.z, v.z * w); m.w = fmaxf(m.w, v.w * w);
    }
    *(float4*)outp = m;
}

// ============================ mma.sync GEMM ================================
// C[M x 128] = A[M x K] @ W[128 x K]^T + bias, fp32 via bf16 hi/lo 3-MMA split.
// 128x128 CTA tile, K chunked by 64. 8 warps in 2(M) x 4(N); warp tile 64x32.
// W is row-major [N][K] == col-major B for mma.row.col. CONCAT: k>=128 reads
// g_neigh. WRITE_H: result goes to g_h.
#define TSTRIDE 72   // bf16 elems per smem tile row (144 B = 9 x 16 B)

template <int K, bool CONCAT, bool WRITE_H>
__global__ void __launch_bounds__(256)
gemm_mma_kernel(const float* __restrict__ A,
                const float* __restrict__ bias,
                float* __restrict__ C, int M, int wofs)
{
    constexpr int NCHUNK = K / 64;
    extern __shared__ __nv_bfloat16 smem[];
    __nv_bfloat16* sAh = smem;
    __nv_bfloat16* sAl = smem + 128 * TSTRIDE;
    __nv_bfloat16* sWh = smem + 2 * 128 * TSTRIDE;
    __nv_bfloat16* sWl = smem + 3 * 128 * TSTRIDE;
    const uint32_t uAh = smem_to_u32(sAh);
    const uint32_t uAl = smem_to_u32(sAl);
    const uint32_t uWh = smem_to_u32(sWh);
    const uint32_t uWl = smem_to_u32(sWl);

    const int tid   = threadIdx.x;
    const int wid   = tid >> 5;
    const int lane  = tid & 31;
    const int row0  = blockIdx.x * 128;
    const int warpM = (wid >> 2) * 64;
    const int warpN = (wid & 3) * 32;

    float c[4][4][4];
    #pragma unroll
    for (int i = 0; i < 4; i++)
        #pragma unroll
        for (int j = 0; j < 4; j++)
            #pragma unroll
            for (int q = 0; q < 4; q++) c[i][j][q] = 0.f;

    // A-load ownership: row ar = tid>>1, cols [(tid&1)*32, +32)
    const int ar  = tid >> 1;
    const int ac0 = (tid & 1) << 5;
    const int gr  = row0 + ar;

    // ldmatrix lane addressing pieces
    const int a_row = (lane & 7) + ((lane >> 3) & 1) * 8;   // + tile row offset
    const int a_col = (lane >> 4) * 8;
    const int b_row = (lane & 7) + ((lane >> 4) & 1) * 8;
    const int b_col = ((lane >> 3) & 1) * 8;

    for (int ch = 0; ch < NCHUNK; ch++) {
        if (ch > 0) __syncthreads();
        const int k0 = ch * 64;

        // ---- A tile: fp32 -> bf16 hi/lo, store to smem ----
        #pragma unroll
        for (int i = 0; i < 4; i++) {
            int col = ac0 + i * 8;
            int gk  = k0 + col;
            float4 va = make_float4(0.f, 0.f, 0.f, 0.f);
            float4 vb = make_float4(0.f, 0.f, 0.f, 0.f);
            if (gr < M) {
                const float* srcp;
                if (!CONCAT || gk < FEAT_D)
                    srcp = A + (size_t)gr * FEAT_D + gk;
                else
                    srcp = g_neigh + (size_t)gr * FEAT_D + (gk - FEAT_D);
                va = *(const float4*)(srcp);
                vb = *(const float4*)(srcp + 4);
            }
            __nv_bfloat162 h0 = __float22bfloat162_rn(make_float2(va.x, va.y));
            __nv_bfloat162 h1 = __float22bfloat162_rn(make_float2(va.z, va.w));
            __nv_bfloat162 h2 = __float22bfloat162_rn(make_float2(vb.x, vb.y));
            __nv_bfloat162 h3 = __float22bfloat162_rn(make_float2(vb.z, vb.w));
            float2 f0 = __bfloat1622float2(h0), f1 = __bfloat1622float2(h1);
            float2 f2 = __bfloat1622float2(h2), f3 = __bfloat1622float2(h3);
            __nv_bfloat162 l0 = __float22bfloat162_rn(make_float2(va.x - f0.x, va.y - f0.y));
            __nv_bfloat162 l1 = __float22bfloat162_rn(make_float2(va.z - f1.x, va.w - f1.y));
            __nv_bfloat162 l2 = __float22bfloat162_rn(make_float2(vb.x - f2.x, vb.y - f2.y));
            __nv_bfloat162 l3 = __float22bfloat162_rn(make_float2(vb.z - f3.x, vb.w - f3.y));
            uint4 hv, lv;
            hv.x = pack_bf2(h0); hv.y = pack_bf2(h1);
            hv.z = pack_bf2(h2); hv.w = pack_bf2(h3);
            lv.x = pack_bf2(l0); lv.y = pack_bf2(l1);
            lv.z = pack_bf2(l2); lv.w = pack_bf2(l3);
            *(uint4*)(sAh + ar * TSTRIDE + col) = hv;
            *(uint4*)(sAl + ar * TSTRIDE + col) = lv;
        }

        // ---- W tiles: copy from pre-split images ----
        {
            const __nv_bfloat16* swh = g_whi + wofs + (size_t)ar * K + k0 + ac0;
            const __nv_bfloat16* swl = g_wlo + wofs + (size_t)ar * K + k0 + ac0;
            #pragma unroll
            for (int j = 0; j < 4; j++) {
                *(uint4*)(sWh + ar * TSTRIDE + ac0 + j * 8) = *(const uint4*)(swh + j * 8);
                *(uint4*)(sWl + ar * TSTRIDE + ac0 + j * 8) = *(const uint4*)(swl + j * 8);
            }
        }
        __syncthreads();

        // ---- compute: 4 k-steps of 16 ----
        #pragma unroll
        for (int ks = 0; ks < 4; ks++) {
            const int k = ks * 16;
            uint32_t bh[2][4], bl[2][4];
            #pragma unroll
            for (int p = 0; p < 2; p++) {
                uint32_t boff = (uint32_t)((warpN + p * 16 + b_row) * TSTRIDE + k + b_col) * 2;
                ldsm_x4(bh[p], uWh + boff);
                ldsm_x4(bl[p], uWl + boff);
            }
            #pragma unroll
            for (int mf = 0; mf < 4; mf++) {
                uint32_t ah[4], al[4];
                uint32_t aoff = (uint32_t)((warpM + mf * 16 + a_row) * TSTRIDE + k + a_col) * 2;
                ldsm_x4(ah, uAh + aoff);
                ldsm_x4(al, uAl + aoff);
                #pragma unroll
                for (int nf = 0; nf < 4; nf++) {
                    const uint32_t* rbh = &bh[nf >> 1][(nf & 1) * 2];
                    const uint32_t* rbl = &bl[nf >> 1][(nf & 1) * 2];
                    mma16816(c[mf][nf], ah, rbh);
                    mma16816(c[mf][nf], ah, rbl);
                    mma16816(c[mf][nf], al, rbh);
                }
            }
        }
    }

    // ---- epilogue ----
    #pragma unroll
    for (int mf = 0; mf < 4; mf++) {
        int r = row0 + warpM + mf * 16 + (lane >> 2);
        #pragma unroll
        for (int nf = 0; nf < 4; nf++) {
            int col = warpN + nf * 8 + 2 * (lane & 3);
            float b0 = bias[col], b1 = bias[col + 1];
            float* base = (WRITE_H ? g_h : C);
            if (r < M) {
                float2 o = make_float2(c[mf][nf][0] + b0, c[mf][nf][1] + b1);
                *(float2*)(base + (size_t)r * FEAT_D + col) = o;
            }
            if (r + 8 < M) {
                float2 o = make_float2(c[mf][nf][2] + b0, c[mf][nf][3] + b1);
                *(float2*)(base + (size_t)(r + 8) * FEAT_D + col) = o;
            }
        }
    }
}

// ---------------------------------------------------------------------------
extern "C" void kernel_launch(void* const* d_in, const int* in_sizes, int n_in,
                              void* d_out, int out_size)
{
    const float* feat    = (const float*)d_in[0];
    const float* weight  = (const float*)d_in[1];
    const void*  src     = d_in[2];
    const void*  dst     = d_in[3];
    const float* W_pool  = (const float*)d_in[4];
    const float* b_pool  = (const float*)d_in[5];
    const float* W_neigh = (const float*)d_in[6];
    const float* b_neigh = (const float*)d_in[7];
    float*       out     = (float*)d_out;

    const int N = in_sizes[0] / FEAT_D;   // 50000
    const int E = in_sizes[1];            // 640000

    const int gemm_blocks = (N + 127) / 128;
    const int scan_blocks = (N + 511) / 512;
    const int SMEM_TOTAL  = 4 * 128 * TSTRIDE * 2;   // 73728 B

    cudaFuncSetAttribute(gemm_mma_kernel<128, false, true>,
                         cudaFuncAttributeMaxDynamicSharedMemorySize, SMEM_TOTAL);
    cudaFuncSetAttribute(gemm_mma_kernel<256, true, false>,
                         cudaFuncAttributeMaxDynamicSharedMemorySize, SMEM_TOTAL);

    // 0) resolve index dtype + precompute bf16 hi/lo weight images
    detect_kernel<<<1, 1>>>(src, E, N);
    prep_w_kernel<<<(128 * 128 + 255) / 256, 256>>>(W_pool, 128, 0);
    prep_w_kernel<<<(128 * 256 + 255) / 256, 256>>>(W_neigh, 256, 128 * 128);

    // 1) h = feat @ W_pool^T + b_pool  (tensor cores)
    gemm_mma_kernel<128, false, true><<<gemm_blocks, 256, SMEM_TOTAL>>>(
        feat, b_pool, nullptr, N, 0);

    // 2) CSR build
    zero_deg_kernel<<<(N + 255) / 256, 256>>>(N);
    count_kernel<<<(E + 255) / 256, 256>>>(dst, E, N);
    scan1_kernel<<<scan_blocks, 512>>>(N);
    scan2_kernel<<<1, 256>>>(scan_blocks);
    scan3_kernel<<<scan_blocks, 512>>>(N, E);
    scatter_kernel<<<(E + 255) / 256, 256>>>(weight, src, dst, E, N);

    // 3) per-node register max
    nodemax_kernel<<<(N * 32 + 255) / 256, 256>>>(N);

    // 4) out = concat(feat, neigh) @ W_neigh^T + b_neigh  (tensor cores)
    gemm_mma_kernel<256, true, false><<<gemm_blocks, 256, SMEM_TOTAL>>>(
        feat, b_neigh, out, N, 128 * 128);
}

// round 9
// speedup vs baseline: 1.6969x; 1.6969x over previous
#include <cuda_runtime.h>
#include <cuda_bf16.h>
#include <cstdint>

#define FEAT_D 128
#define MAX_NODES 50176
#define MAX_EDGES 650240
#define TSTRIDE 72            // bf16 per smem row (144 B)
#define TILE_HALF (128 * TSTRIDE)          // bf16 elems per tensor-half
#define BUF_BF16  (4 * TILE_HALF)          // A_hi, A_lo, W_hi, W_lo
#define SMEM_BYTES (2 * BUF_BF16 * 2)      // double buffered: 147456 B

// ---- scratch (__device__ globals; no allocation allowed) ----
__device__ float g_h[MAX_NODES * FEAT_D];          // pooled features (fp32, for max)
__device__ __nv_bfloat16 g_fhi[MAX_NODES * FEAT_D];
__device__ __nv_bfloat16 g_flo[MAX_NODES * FEAT_D];
__device__ __nv_bfloat16 g_nhi[MAX_NODES * FEAT_D];
__device__ __nv_bfloat16 g_nlo[MAX_NODES * FEAT_D];
__device__ int   g_deg[MAX_NODES];
__device__ int   g_incl[MAX_NODES];
__device__ int   g_bsum[256];
__device__ int   g_bbase[256];
__device__ int   g_offs[MAX_NODES + 1];
__device__ int   g_cursor[MAX_NODES];
__device__ int2  g_rec[MAX_EDGES];
__device__ int   g_idx64;
// bf16 hi/lo weight images, row-major [128][K]: W_pool at 0 (K=128), W_neigh at 128*128 (K=256)
__device__ __nv_bfloat16 g_whi[128 * 384];
__device__ __nv_bfloat16 g_wlo[128 * 384];

// ============================ helpers ======================================
__device__ __forceinline__ uint32_t smem_to_u32(const void* p) {
    uint32_t a;
    asm("{ .reg .u64 t; cvta.to.shared.u64 t, %1; cvt.u32.u64 %0, t; }" : "=r"(a) : "l"(p));
    return a;
}
__device__ __forceinline__ uint32_t pack_bf2(__nv_bfloat162 v) {
    return ((uint32_t)__bfloat16_as_ushort(v.y) << 16) |
            (uint32_t)__bfloat16_as_ushort(v.x);
}
__device__ __forceinline__ void ldsm_x4(uint32_t* r, uint32_t addr) {
    asm volatile("ldmatrix.sync.aligned.m8n8.x4.shared.b16 {%0,%1,%2,%3}, [%4];"
        : "=r"(r[0]), "=r"(r[1]), "=r"(r[2]), "=r"(r[3]) : "r"(addr));
}
__device__ __forceinline__ void mma16816(float* c, const uint32_t* a, const uint32_t* b) {
    asm volatile("mma.sync.aligned.m16n8k16.row.col.f32.bf16.bf16.f32 "
        "{%0,%1,%2,%3}, {%4,%5,%6,%7}, {%8,%9}, {%0,%1,%2,%3};"
        : "+f"(c[0]), "+f"(c[1]), "+f"(c[2]), "+f"(c[3])
        : "r"(a[0]), "r"(a[1]), "r"(a[2]), "r"(a[3]), "r"(b[0]), "r"(b[1]));
}
__device__ __forceinline__ void cp_async16(uint32_t saddr, const void* gaddr) {
    asm volatile("cp.async.cg.shared.global [%0], [%1], 16;" :: "r"(saddr), "l"(gaddr));
}
#define CP_COMMIT() asm volatile("cp.async.commit_group;" ::: "memory")
#define CP_WAIT1()  asm volatile("cp.async.wait_group 1;" ::: "memory")
#define CP_WAIT0()  asm volatile("cp.async.wait_group 0;" ::: "memory")

// ============================ misc kernels =================================
__global__ void detect_kernel(const void* src, int E, int N) {
    if (threadIdx.x == 0 && blockIdx.x == 0) {
        const long long* p = (const long long*)src;
        int n = E < 256 ? E : 256;
        int ok = 1;
        for (int i = 0; i < n; i++) {
            long long v = p[i];
            if (v < 0 || v >= (long long)N) { ok = 0; break; }
        }
        g_idx64 = ok;
    }
}
__device__ __forceinline__ int load_idx(const void* p, int i) {
    return g_idx64 ? (int)((const long long*)p)[i] : ((const int*)p)[i];
}

// Split W (row-major [128][K] fp32) into bf16 hi/lo row-major images.
__global__ void prep_w_kernel(const float* __restrict__ W, int K, int wofs) {
    int e = blockIdx.x * blockDim.x + threadIdx.x;
    if (e >= 128 * K) return;
    float v = W[e];
    __nv_bfloat16 h = __float2bfloat16(v);
    __nv_bfloat16 l = __float2bfloat16(v - __bfloat162float(h));
    g_whi[wofs + e] = h;
    g_wlo[wofs + e] = l;
}

// Split feat into bf16 hi/lo images (shared by both GEMMs).
__global__ void prep_feat_kernel(const float* __restrict__ feat, int n4) {
    int i = blockIdx.x * blockDim.x + threadIdx.x;
    if (i >= n4) return;
    float4 v = ((const float4*)feat)[i];
    __nv_bfloat162 h0 = __float22bfloat162_rn(make_float2(v.x, v.y));
    __nv_bfloat162 h1 = __float22bfloat162_rn(make_float2(v.z, v.w));
    float2 f0 = __bfloat1622float2(h0), f1 = __bfloat1622float2(h1);
    __nv_bfloat162 l0 = __float22bfloat162_rn(make_float2(v.x - f0.x, v.y - f0.y));
    __nv_bfloat162 l1 = __float22bfloat162_rn(make_float2(v.z - f1.x, v.w - f1.y));
    ((uint2*)g_fhi)[i] = make_uint2(pack_bf2(h0), pack_bf2(h1));
    ((uint2*)g_flo)[i] = make_uint2(pack_bf2(l0), pack_bf2(l1));
}

// ============================ CSR build ====================================
__global__ void zero_deg_kernel(int n) {
    int i = blockIdx.x * blockDim.x + threadIdx.x;
    if (i < n) g_deg[i] = 0;
}
__global__ void count_kernel(const void* __restrict__ dst, int E, int N) {
    int e = blockIdx.x * blockDim.x + threadIdx.x;
    if (e >= E) return;
    int d = load_idx(dst, e);
    if ((unsigned)d < (unsigned)N) atomicAdd(&g_deg[d], 1);
}
__global__ void scan1_kernel(int n) {
    __shared__ int s[512];
    int tid = threadIdx.x;
    int i = blockIdx.x * 512 + tid;
    int v = (i < n) ? g_deg[i] : 0;
    s[tid] = v;
    __syncthreads();
    #pragma unroll
    for (int off = 1; off < 512; off <<= 1) {
        int t = (tid >= off) ? s[tid - off] : 0;
        __syncthreads();
        s[tid] += t;
        __syncthreads();
    }
    if (i < n) g_incl[i] = s[tid];
    if (tid == 511) g_bsum[blockIdx.x] = s[511];
}
__global__ void scan2_kernel(int nblocks) {
    __shared__ int s[256];
    int tid = threadIdx.x;
    int v = (tid < nblocks) ? g_bsum[tid] : 0;
    s[tid] = v;
    __syncthreads();
    #pragma unroll
    for (int off = 1; off < 256; off <<= 1) {
        int t = (tid >= off) ? s[tid - off] : 0;
        __syncthreads();
        s[tid] += t;
        __syncthreads();
    }
    if (tid < nblocks) g_bbase[tid] = s[tid] - v;
}
__global__ void scan3_kernel(int n, int E) {
    int i = blockIdx.x * 512 + threadIdx.x;
    if (i >= n) return;
    int ex = g_incl[i] - g_deg[i] + g_bbase[blockIdx.x];
    g_offs[i]   = ex;
    g_cursor[i] = ex;
    if (i == n - 1) g_offs[n] = E;
}
__global__ void scatter_kernel(const float* __restrict__ weight,
                               const void* __restrict__ src,
                               const void* __restrict__ dst,
                               int E, int N) {
    int e = blockIdx.x * blockDim.x + threadIdx.x;
    if (e >= E) return;
    int d = load_idx(dst, e);
    int s = load_idx(src, e);
    if ((unsigned)d >= (unsigned)N || (unsigned)s >= (unsigned)N) return;
    int pos = atomicAdd(&g_cursor[d], 1);
    g_rec[pos] = make_int2(s, __float_as_int(weight[e]));
}

// ============================ node max =====================================
// One warp per node; result written directly as bf16 hi/lo (GEMM2 operand).
__global__ void __launch_bounds__(256)
nodemax_kernel(int N) {
    int warp = (blockIdx.x * blockDim.x + threadIdx.x) >> 5;
    int lane = threadIdx.x & 31;
    if (warp >= N) return;

    int beg = g_offs[warp];
    int end = g_offs[warp + 1];

    float4 m;
    if (beg == end) {
        m = make_float4(0.f, 0.f, 0.f, 0.f);
    } else {
        const float NEG = -3.402823466e+38f;
        m = make_float4(NEG, NEG, NEG, NEG);
        int e = beg;
        for (; e + 4 <= end; e += 4) {
            int2 r0 = g_rec[e + 0];
            int2 r1 = g_rec[e + 1];
            int2 r2 = g_rec[e + 2];
            int2 r3 = g_rec[e + 3];
            float4 v0 = *(const float4*)(g_h + (size_t)r0.x * FEAT_D + lane * 4);
            float4 v1 = *(const float4*)(g_h + (size_t)r1.x * FEAT_D + lane * 4);
            float4 v2 = *(const float4*)(g_h + (size_t)r2.x * FEAT_D + lane * 4);
            float4 v3 = *(const float4*)(g_h + (size_t)r3.x * FEAT_D + lane * 4);
            float w0 = __int_as_float(r0.y), w1 = __int_as_float(r1.y);
            float w2 = __int_as_float(r2.y), w3 = __int_as_float(r3.y);
            m.x = fmaxf(m.x, v0.x * w0); m.y = fmaxf(m.y, v0.y * w0);
            m.z = fmaxf(m.z, v0.z * w0); m.w = fmaxf(m.w, v0.w * w0);
            m.x = fmaxf(m.x, v1.x * w1); m.y = fmaxf(m.y, v1.y * w1);
            m.z = fmaxf(m.z, v1.z * w1); m.w = fmaxf(m.w, v1.w * w1);
            m.x = fmaxf(m.x, v2.x * w2); m.y = fmaxf(m.y, v2.y * w2);
            m.z = fmaxf(m.z, v2.z * w2); m.w = fmaxf(m.w, v2.w * w2);
            m.x = fmaxf(m.x, v3.x * w3); m.y = fmaxf(m.y, v3.y * w3);
            m.z = fmaxf(m.z, v3.z * w3); m.w = fmaxf(m.w, v3.w * w3);
        }
        for (; e < end; e++) {
            int2 r = g_rec[e];
            float w = __int_as_float(r.y);
            float4 v = *(const float4*)(g_h + (size_t)r.x * FEAT_D + lane * 4);
            m.x = fmaxf(m.x, v.x * w); m.y = fmaxf(m.y, v.y * w);
            m.z = fmaxf(m.z, v.z * w); m.w = fmaxf(m.w, v.w * w);
        }
    }
    __nv_bfloat162 h0 = __float22bfloat162_rn(make_float2(m.x, m.y));
    __nv_bfloat162 h1 = __float22bfloat162_rn(make_float2(m.z, m.w));
    float2 f0 = __bfloat1622float2(h0), f1 = __bfloat1622float2(h1);
    __nv_bfloat162 l0 = __float22bfloat162_rn(make_float2(m.x - f0.x, m.y - f0.y));
    __nv_bfloat162 l1 = __float22bfloat162_rn(make_float2(m.z - f1.x, m.w - f1.y));
    int slot = warp * 32 + lane;
    ((uint2*)g_nhi)[slot] = make_uint2(pack_bf2(h0), pack_bf2(h1));
    ((uint2*)g_nlo)[slot] = make_uint2(pack_bf2(l0), pack_bf2(l1));
}

// ============================ mma.sync GEMM ================================
// C[M x 128] = A[M x K] @ W[128 x K]^T + bias, fp32 via bf16 hi/lo 3-MMA split.
// A/W already pre-split bf16 in gmem. 128x128 CTA tile, K chunked by 64.
// 512 threads, 16 warps in 4(M) x 4(N), warp tile 32x32. cp.async double buffer.
template <int K, bool CONCAT, bool WRITE_H>
__device__ __forceinline__ void load_chunk(int ch, int buf, int tid, int row0, int M,
                                           int wofs, uint32_t sU) {
    const __nv_bfloat16 *Ah, *Al;
    if (!CONCAT || ch < 2) { Ah = g_fhi; Al = g_flo; }
    else                   { Ah = g_nhi; Al = g_nlo; }
    const int k0  = (ch & 1) * 64;     // col offset within 128-wide A source
    const int kw0 = ch * 64;           // col offset within W row (K wide)
    uint32_t base = sU + (uint32_t)buf * (BUF_BF16 * 2);
    #pragma unroll
    for (int t = 0; t < 2; t++) {
        int idx = tid + t * 512;       // 0..1023
        int row = idx >> 3;
        int seg = idx & 7;
        int gr = row0 + row; if (gr > M - 1) gr = M - 1;
        uint32_t d = base + (uint32_t)(row * (TSTRIDE * 2) + seg * 16);
        cp_async16(d,                     Ah + (size_t)gr * FEAT_D + k0 + seg * 8);
        cp_async16(d + 1 * TILE_HALF * 2, Al + (size_t)gr * FEAT_D + k0 + seg * 8);
        cp_async16(d + 2 * TILE_HALF * 2, g_whi + wofs + (size_t)row * K + kw0 + seg * 8);
        cp_async16(d + 3 * TILE_HALF * 2, g_wlo + wofs + (size_t)row * K + kw0 + seg * 8);
    }
}

template <int K, bool CONCAT, bool WRITE_H>
__global__ void __launch_bounds__(512)
gemm_mma_kernel(const float* __restrict__ bias, float* __restrict__ C, int M, int wofs)
{
    constexpr int NCHUNK = K / 64;
    extern __shared__ __nv_bfloat16 smem[];
    const uint32_t sU = smem_to_u32(smem);

    const int tid   = threadIdx.x;
    const int wid   = tid >> 5;
    const int lane  = tid & 31;
    const int row0  = blockIdx.x * 128;
    const int warpM = (wid >> 2) * 32;
    const int warpN = (wid & 3) * 32;

    float c[2][4][4];
    #pragma unroll
    for (int i = 0; i < 2; i++)
        #pragma unroll
        for (int j = 0; j < 4; j++)
            #pragma unroll
            for (int q = 0; q < 4; q++) c[i][j][q] = 0.f;

    const int a_row = (lane & 7) + ((lane >> 3) & 1) * 8;
    const int a_col = (lane >> 4) * 8;
    const int b_row = (lane & 7) + ((lane >> 4) & 1) * 8;
    const int b_col = ((lane >> 3) & 1) * 8;

    load_chunk<K, CONCAT, WRITE_H>(0, 0, tid, row0, M, wofs, sU);
    CP_COMMIT();

    for (int ch = 0; ch < NCHUNK; ch++) {
        if (ch + 1 < NCHUNK) {
            load_chunk<K, CONCAT, WRITE_H>(ch + 1, (ch + 1) & 1, tid, row0, M, wofs, sU);
            CP_COMMIT();
            CP_WAIT1();
        } else {
            CP_WAIT0();
        }
        __syncthreads();

        const uint32_t bb  = sU + (uint32_t)(ch & 1) * (BUF_BF16 * 2);
        const uint32_t uAh = bb;
        const uint32_t uAl = bb + 1 * TILE_HALF * 2;
        const uint32_t uWh = bb + 2 * TILE_HALF * 2;
        const uint32_t uWl = bb + 3 * TILE_HALF * 2;

        #pragma unroll
        for (int ks = 0; ks < 4; ks++) {
            const int k = ks * 16;
            uint32_t bh[2][4], bl[2][4];
            #pragma unroll
            for (int p = 0; p < 2; p++) {
                uint32_t boff = (uint32_t)((warpN + p * 16 + b_row) * TSTRIDE + k + b_col) * 2;
                ldsm_x4(bh[p], uWh + boff);
                ldsm_x4(bl[p], uWl + boff);
            }
            #pragma unroll
            for (int mf = 0; mf < 2; mf++) {
                uint32_t ah[4], al[4];
                uint32_t aoff = (uint32_t)((warpM + mf * 16 + a_row) * TSTRIDE + k + a_col) * 2;
                ldsm_x4(ah, uAh + aoff);
                ldsm_x4(al, uAl + aoff);
                #pragma unroll
                for (int nf = 0; nf < 4; nf++) {
                    const uint32_t* rbh = &bh[nf >> 1][(nf & 1) * 2];
                    const uint32_t* rbl = &bl[nf >> 1][(nf & 1) * 2];
                    mma16816(c[mf][nf], ah, rbh);
                    mma16816(c[mf][nf], ah, rbl);
                    mma16816(c[mf][nf], al, rbh);
                }
            }
        }
        if (ch + 1 < NCHUNK) __syncthreads();   // protect buffer reuse
    }

    // ---- epilogue ----
    #pragma unroll
    for (int mf = 0; mf < 2; mf++) {
        int r = row0 + warpM + mf * 16 + (lane >> 2);
        #pragma unroll
        for (int nf = 0; nf < 4; nf++) {
            int col = warpN + nf * 8 + 2 * (lane & 3);
            float b0 = bias[col], b1 = bias[col + 1];
            float* base = (WRITE_H ? g_h : C);
            if (r < M) {
                float2 o = make_float2(c[mf][nf][0] + b0, c[mf][nf][1] + b1);
                *(float2*)(base + (size_t)r * FEAT_D + col) = o;
            }
            if (r + 8 < M) {
                float2 o = make_float2(c[mf][nf][2] + b0, c[mf][nf][3] + b1);
                *(float2*)(base + (size_t)(r + 8) * FEAT_D + col) = o;
            }
        }
    }
}

// ---------------------------------------------------------------------------
extern "C" void kernel_launch(void* const* d_in, const int* in_sizes, int n_in,
                              void* d_out, int out_size)
{
    const float* feat    = (const float*)d_in[0];
    const float* weight  = (const float*)d_in[1];
    const void*  src     = d_in[2];
    const void*  dst     = d_in[3];
    const float* W_pool  = (const float*)d_in[4];
    const float* b_pool  = (const float*)d_in[5];
    const float* W_neigh = (const float*)d_in[6];
    const float* b_neigh = (const float*)d_in[7];
    float*       out     = (float*)d_out;

    const int N = in_sizes[0] / FEAT_D;   // 50000
    const int E = in_sizes[1];            // 640000

    const int gemm_blocks = (N + 127) / 128;
    const int scan_blocks = (N + 511) / 512;

    cudaFuncSetAttribute(gemm_mma_kernel<128, false, true>,
                         cudaFuncAttributeMaxDynamicSharedMemorySize, SMEM_BYTES);
    cudaFuncSetAttribute(gemm_mma_kernel<256, true, false>,
                         cudaFuncAttributeMaxDynamicSharedMemorySize, SMEM_BYTES);

    // 0) index dtype + pre-split weights and feat into bf16 hi/lo
    detect_kernel<<<1, 1>>>(src, E, N);
    prep_w_kernel<<<(128 * 128 + 255) / 256, 256>>>(W_pool, 128, 0);
    prep_w_kernel<<<(128 * 256 + 255) / 256, 256>>>(W_neigh, 256, 128 * 128);
    prep_feat_kernel<<<(N * FEAT_D / 4 + 255) / 256, 256>>>(feat, N * FEAT_D / 4);

    // 1) h = feat @ W_pool^T + b_pool  (tensor cores, pipelined)
    gemm_mma_kernel<128, false, true><<<gemm_blocks, 512, SMEM_BYTES>>>(
        b_pool, nullptr, N, 0);

    // 2) CSR build
    zero_deg_kernel<<<(N + 255) / 256, 256>>>(N);
    count_kernel<<<(E + 255) / 256, 256>>>(dst, E, N);
    scan1_kernel<<<scan_blocks, 512>>>(N);
    scan2_kernel<<<1, 256>>>(scan_blocks);
    scan3_kernel<<<scan_blocks, 512>>>(N, E);
    scatter_kernel<<<(E + 255) / 256, 256>>>(weight, src, dst, E, N);

    // 3) per-node register max -> bf16 hi/lo neigh images
    nodemax_kernel<<<(N * 32 + 255) / 256, 256>>>(N);

    // 4) out = concat(feat, neigh) @ W_neigh^T + b_neigh
    gemm_mma_kernel<256, true, false><<<gemm_blocks, 512, SMEM_BYTES>>>(
        b_neigh, out, N, 128 * 128);
}